// round 9
// baseline (speedup 1.0000x reference)
#include <cuda_runtime.h>
#include <math.h>
#include <stdint.h>

#define B   32
#define LL  128
#define LR  128
#define D   512
#define A   128
#define OC  259   // 1+64 | 64 | 1+64 | 1+64

// ---- scratch (static device globals; no runtime allocation) ----
__device__ float g_algt[(B*LL + B*LR) * A];
__device__ float g_att[B*LL*D];
__device__ float g_probs[B*LL*LR];
__device__ float g_invnrt[B*LR];
__device__ int   g_idx[B*LL];
__device__ float g_mx[128*B*LL];          // raw r-half maxes: [(m*2+rh)*B + b]*128 + l
// L pre-split to bf16 hi/lo, stored pre-swizzled as (b,chunk) tiles of
// 128 rows x 128B (XOR swizzle); chunk = 64 d's.
__device__ __align__(16) unsigned char g_Lh[B*8*16384];
__device__ __align__(16) unsigned char g_Ll[B*8*16384];

__device__ __forceinline__ uint32_t swz(uint32_t x){ return x ^ ((x >> 3) & 0x70u); }
__device__ __forceinline__ uint32_t smem_u32(const void* p){
    uint32_t a;
    asm("{ .reg .u64 t; cvta.to.shared.u64 t, %1; cvt.u32.u64 %0, t; }" : "=r"(a) : "l"(p));
    return a;
}
__device__ __forceinline__ void split2(float x0, float x1, uint32_t& h, uint32_t& l){
    asm("cvt.rn.bf16x2.f32 %0, %1, %2;" : "=r"(h) : "f"(x1), "f"(x0));
    float h0 = __uint_as_float(h << 16), h1 = __uint_as_float(h & 0xffff0000u);
    asm("cvt.rn.bf16x2.f32 %0, %1, %2;" : "=r"(l) : "f"(x1 - h1), "f"(x0 - h0));
}

#define LDSM4(r0,r1,r2,r3,addr) \
    asm volatile("ldmatrix.sync.aligned.m8n8.x4.shared.b16 {%0,%1,%2,%3}, [%4];" \
        : "=r"(r0),"=r"(r1),"=r"(r2),"=r"(r3) : "r"(addr))
#define CP16(s,g) \
    asm volatile("cp.async.cg.shared.global [%0], [%1], 16;" :: "r"(s), "l"(g))
#define CPCOMMIT() asm volatile("cp.async.commit_group;")
#define CPWAIT1()  asm volatile("cp.async.wait_group 1;")
#define CPWAIT0()  asm volatile("cp.async.wait_group 0;")

__device__ __forceinline__ void mma_bf16(float* d, const uint32_t* a, const uint32_t* b){
    asm volatile("mma.sync.aligned.m16n8k16.row.col.f32.bf16.bf16.f32 "
        "{%0,%1,%2,%3}, {%4,%5,%6,%7}, {%8,%9}, {%0,%1,%2,%3};"
        : "+f"(d[0]),"+f"(d[1]),"+f"(d[2]),"+f"(d[3])
        : "r"(a[0]),"r"(a[1]),"r"(a[2]),"r"(a[3]), "r"(b[0]),"r"(b[1]));
}

// ============================================================================
// k_split: L (fp32) -> g_Lh/g_Ll bf16 hi/lo swizzled tiles. grid (8, B).
// ============================================================================
__global__ void __launch_bounds__(256) k_split(const float* __restrict__ L)
{
    int c = blockIdx.x, b = blockIdx.y, t = threadIdx.x;
    const float* Lb = L + ((size_t)b << 16) + c*64;
    size_t tile = ((size_t)(b*8 + c)) << 14;
    #pragma unroll
    for (int i = 0; i < 4; i++){
        int f = i*256 + t; int row = f >> 3, q = f & 7;
        const float* src = Lb + (size_t)row*512 + q*8;
        float4 v0 = *(const float4*)src, v1 = *(const float4*)(src + 4);
        uint32_t h01,l01,h23,l23,h45,l45,h67,l67;
        split2(v0.x, v0.y, h01, l01);
        split2(v0.z, v0.w, h23, l23);
        split2(v1.x, v1.y, h45, l45);
        split2(v1.z, v1.w, h67, l67);
        uint32_t off = swz((uint32_t)(row*128 + q*16));
        *(uint4*)(g_Lh + tile + off) = make_uint4(h01, h23, h45, h67);
        *(uint4*)(g_Ll + tile + off) = make_uint4(l01, l23, l45, l67);
    }
}

// ============================================================================
// k_mpool_mma: CTA = (m*2+rh, b).  Tile 128 l x 64 r (rh selects r-half).
// C[l,r] = sum_d L[l,d]*(R[r,d]*K_m[d]);  writes max_r(tile) to g_mx (no tanh).
// A = L hi/lo (pre-split, cp.async dbl-buffered), B = (R*K_m) hi/lo in smem.
// 8 warps = 2(l) x 4(r); warp tile 64 x 16; acc 4x2 mma positions (32 regs).
// dyn smem: A[2][h16K|l16K]=64K | Bh 8K | Bl 8K | sK 2K = 83968 B -> occ 2
// ============================================================================
__global__ void __launch_bounds__(256, 2) k_mpool_mma(
    const float* __restrict__ Rr, const float* __restrict__ Kmp)
{
    extern __shared__ __align__(16) unsigned char dyn[];
    int bx = blockIdx.x, b = blockIdx.y;
    int m = bx >> 1, rh = bx & 1;
    int t = threadIdx.x, wid = t >> 5, lane = t & 31;
    uint32_t base = smem_u32(dyn);
    uint32_t Abuf[2] = {base, base + 32768};
    uint32_t Bh = base + 65536, Bl = base + 73728;
    float* sK = (float*)(dyn + 81920);
    for (int i = t; i < 512; i += 256) sK[i] = Kmp[(size_t)m*512 + i];

    // preload A chunk 0
    {
        const unsigned char* gh = g_Lh + (((size_t)(b*8)) << 14);
        const unsigned char* gl = g_Ll + (((size_t)(b*8)) << 14);
        #pragma unroll
        for (int i = 0; i < 4; i++){
            uint32_t o = (uint32_t)(i*256 + t) * 16;
            CP16(Abuf[0] + o, gh + o);
            CP16(Abuf[0] + 16384 + o, gl + o);
        }
        CPCOMMIT();
    }
    __syncthreads();

    int wl = wid >> 2, wn = wid & 3;       // wl 0..1, wn 0..3
    float acc[4][2][4];
    #pragma unroll
    for (int i = 0; i < 4; i++)
        #pragma unroll
        for (int j = 0; j < 2; j++)
            #pragma unroll
            for (int k = 0; k < 4; k++) acc[i][j][k] = 0.f;

    int rowA = lane & 15;
    int cbA  = lane >> 4;
    int rowB = ((lane >> 4) & 1) * 8 + (lane & 7);
    int cbB  = (lane >> 3) & 1;

    const float* Rb = Rr + ((size_t)b << 16) + (size_t)(rh*64)*512;
    int rrow = t >> 3, rq = t & 7;        // build coords: rows rrow, rrow+32

    for (int c = 0; c < 8; c++){
        if (c < 7){
            uint32_t nb = Abuf[(c+1) & 1];
            const unsigned char* gh = g_Lh + (((size_t)(b*8 + c+1)) << 14);
            const unsigned char* gl = g_Ll + (((size_t)(b*8 + c+1)) << 14);
            #pragma unroll
            for (int i = 0; i < 4; i++){
                uint32_t o = (uint32_t)(i*256 + t) * 16;
                CP16(nb + o, gh + o);
                CP16(nb + 16384 + o, gl + o);
            }
            CPCOMMIT();
        }
        // build B = (R*K_m) hi/lo for this CTA's 64 r rows
        {
            float4 k0 = *(const float4*)(sK + c*64 + rq*8);
            float4 k1 = *(const float4*)(sK + c*64 + rq*8 + 4);
            #pragma unroll
            for (int i = 0; i < 2; i++){
                int row = rrow + i*32;
                const float* src = Rb + (size_t)row*512 + c*64 + rq*8;
                float4 r0 = *(const float4*)src, r1 = *(const float4*)(src + 4);
                uint32_t h01,l01,h23,l23,h45,l45,h67,l67;
                split2(r0.x*k0.x, r0.y*k0.y, h01, l01);
                split2(r0.z*k0.z, r0.w*k0.w, h23, l23);
                split2(r1.x*k1.x, r1.y*k1.y, h45, l45);
                split2(r1.z*k1.z, r1.w*k1.w, h67, l67);
                uint32_t off = swz((uint32_t)(row*128 + rq*16));
                asm volatile("st.shared.v4.b32 [%0], {%1,%2,%3,%4};"
                             :: "r"(Bh+off), "r"(h01), "r"(h23), "r"(h45), "r"(h67));
                asm volatile("st.shared.v4.b32 [%0], {%1,%2,%3,%4};"
                             :: "r"(Bl+off), "r"(l01), "r"(l23), "r"(l45), "r"(l67));
            }
        }
        if (c < 7) { CPWAIT1(); } else { CPWAIT0(); }
        __syncthreads();

        uint32_t Ah = Abuf[c & 1], Al = Ah + 16384;
        #pragma unroll
        for (int ks = 0; ks < 4; ks++){
            uint32_t aoffs[4];
            #pragma unroll
            for (int mt = 0; mt < 4; mt++)
                aoffs[mt] = swz((uint32_t)((wl*64 + mt*16 + rowA)*128 + ks*32 + cbA*16));
            uint32_t boff = swz((uint32_t)((wn*16 + rowB)*128 + ks*32 + cbB*16));

            uint32_t bh_[2][2];
            LDSM4(bh_[0][0], bh_[0][1], bh_[1][0], bh_[1][1], Bh + boff);
            {   // AlBh
                uint32_t al_[4][4];
                #pragma unroll
                for (int mt = 0; mt < 4; mt++)
                    LDSM4(al_[mt][0], al_[mt][1], al_[mt][2], al_[mt][3], Al + aoffs[mt]);
                #pragma unroll
                for (int mt = 0; mt < 4; mt++)
                    #pragma unroll
                    for (int nt = 0; nt < 2; nt++)
                        mma_bf16(acc[mt][nt], al_[mt], bh_[nt]);
            }
            uint32_t ah_[4][4];
            #pragma unroll
            for (int mt = 0; mt < 4; mt++)
                LDSM4(ah_[mt][0], ah_[mt][1], ah_[mt][2], ah_[mt][3], Ah + aoffs[mt]);
            #pragma unroll
            for (int mt = 0; mt < 4; mt++)
                #pragma unroll
                for (int nt = 0; nt < 2; nt++)
                    mma_bf16(acc[mt][nt], ah_[mt], bh_[nt]);
            {   // AhBl
                uint32_t bl_[2][2];
                LDSM4(bl_[0][0], bl_[0][1], bl_[1][0], bl_[1][1], Bl + boff);
                #pragma unroll
                for (int mt = 0; mt < 4; mt++)
                    #pragma unroll
                    for (int nt = 0; nt < 2; nt++)
                        mma_bf16(acc[mt][nt], ah_[mt], bl_[nt]);
            }
        }
        __syncthreads();
    }

    // epilogue: max over this CTA's 64 r  ->  g_mx (raw, tanh in k_comb)
    float* red = (float*)dyn;   // 128 x 4
    int g = lane >> 2, tg = lane & 3;
    #pragma unroll
    for (int mt = 0; mt < 4; mt++){
        float m0 = -1e30f, m1 = -1e30f;
        #pragma unroll
        for (int nt = 0; nt < 2; nt++){
            m0 = fmaxf(m0, fmaxf(acc[mt][nt][0], acc[mt][nt][1]));
            m1 = fmaxf(m1, fmaxf(acc[mt][nt][2], acc[mt][nt][3]));
        }
        m0 = fmaxf(m0, __shfl_xor_sync(0xffffffffu, m0, 1));
        m0 = fmaxf(m0, __shfl_xor_sync(0xffffffffu, m0, 2));
        m1 = fmaxf(m1, __shfl_xor_sync(0xffffffffu, m1, 1));
        m1 = fmaxf(m1, __shfl_xor_sync(0xffffffffu, m1, 2));
        if (tg == 0){
            red[(wl*64 + mt*16 + g)*4 + wn]     = m0;
            red[(wl*64 + mt*16 + g + 8)*4 + wn] = m1;
        }
    }
    __syncthreads();
    if (t < 128){
        float v = fmaxf(fmaxf(red[t*4], red[t*4+1]), fmaxf(red[t*4+2], red[t*4+3]));
        g_mx[((size_t)bx*B + b)*128 + t] = v;
    }
}

// ============================================================================
// k_comb: out[b,l,65+m] = tanh(max(g_mx[2m half], g_mx[2m+1 half])). grid 1024.
// ============================================================================
__global__ void __launch_bounds__(256) k_comb(float* __restrict__ out)
{
    int idx = blockIdx.x*256 + threadIdx.x;     // 262144 total
    int m = idx & 63, l = (idx >> 6) & 127, b = idx >> 13;
    float a = g_mx[((size_t)(m*2)*B   + b)*128 + l];
    float c = g_mx[((size_t)(m*2+1)*B + b)*128 + l];
    out[(size_t)(b*128 + l)*OC + 65 + m] = tanhf(fmaxf(a, c));
}

// ============================================================================
// k_algt: a_lt = tanh(L@W1)*diag ; a_rt = tanh(R@W1).
// ============================================================================
__global__ void __launch_bounds__(256) k_algt(
    const float* __restrict__ Lr, const float* __restrict__ Rr,
    const float* __restrict__ W1, const float* __restrict__ diag)
{
    __shared__ float Xs[16][17];
    __shared__ float Ws[16][A];
    int row0 = blockIdx.x * 16;
    int t = threadIdx.x;
    int c  = t & 127;
    int rh = t >> 7;
    float acc[8];
    #pragma unroll
    for (int i = 0; i < 8; i++) acc[i] = 0.f;

    for (int kt = 0; kt < D; kt += 16) {
        #pragma unroll
        for (int i = 0; i < 8; i++) {
            int f = i * 256 + t;
            int k = f >> 7, a = f & 127;
            Ws[k][a] = W1[(kt + k) * A + a];
        }
        {
            int r = t >> 4, k = t & 15;
            int grow = row0 + r;
            const float* X = (grow < B*LL) ? (Lr + (size_t)grow * D)
                                           : (Rr + (size_t)(grow - B*LL) * D);
            Xs[r][k] = X[kt + k];
        }
        __syncthreads();
        #pragma unroll
        for (int k = 0; k < 16; k++) {
            float w = Ws[k][c];
            #pragma unroll
            for (int i = 0; i < 8; i++)
                acc[i] = fmaf(Xs[rh*8 + i][k], w, acc[i]);
        }
        __syncthreads();
    }
    #pragma unroll
    for (int i = 0; i < 8; i++) {
        int grow = row0 + rh*8 + i;
        float v = tanhf(acc[i]);
        if (grow < B*LL) v *= diag[c];
        g_algt[(size_t)grow * A + c] = v;
    }
}

// ============================================================================
// k_score: per block (b, 16 l's): scores -> softmax -> g_probs. grid (8, B).
// ============================================================================
__global__ void __launch_bounds__(256) k_score()
{
    __shared__ float alt[16][129];
    __shared__ float art[16][129];
    __shared__ float S[16][132];

    int b  = blockIdx.y;
    int l0 = blockIdx.x * 16;
    int t  = threadIdx.x;
    int li = t >> 4, rj = t & 15;

    #pragma unroll
    for (int i = 0; i < 8; i++) {
        int f = i * 256 + t;
        int r = f >> 7, a = f & 127;
        alt[r][a] = g_algt[(size_t)(b*LL + l0 + r) * A + a];
    }

    for (int rc = 0; rc < 8; rc++) {
        __syncthreads();
        #pragma unroll
        for (int i = 0; i < 8; i++) {
            int f = i * 256 + t;
            int r = f >> 7, a = f & 127;
            art[r][a] = g_algt[(size_t)(B*LL + b*LR + rc*16 + r) * A + a];
        }
        __syncthreads();
        float s = 0.f;
        #pragma unroll 4
        for (int a = 0; a < A; a++) s = fmaf(alt[li][a], art[rj][a], s);
        S[li][rc*16 + rj] = s;
    }
    __syncthreads();

    int w = t >> 5, lane = t & 31;
    #pragma unroll
    for (int rr = w*2; rr < w*2 + 2; rr++) {
        float v0 = S[rr][lane], v1 = S[rr][lane+32],
              v2 = S[rr][lane+64], v3 = S[rr][lane+96];
        float m0 = fmaxf(fmaxf(v0,v1), fmaxf(v2,v3));
        #pragma unroll
        for (int off = 16; off; off >>= 1) m0 = fmaxf(m0, __shfl_xor_sync(0xffffffffu, m0, off));
        float e0 = expf(v0-m0), e1 = expf(v1-m0), e2 = expf(v2-m0), e3 = expf(v3-m0);
        float sum = e0+e1+e2+e3;
        #pragma unroll
        for (int off = 16; off; off >>= 1) sum += __shfl_xor_sync(0xffffffffu, sum, off);
        float inv = 1.f / sum;
        float* pp = g_probs + (size_t)(b*LL + l0 + rr)*LR;
        pp[lane] = e0*inv; pp[lane+32] = e1*inv;
        pp[lane+64] = e2*inv; pp[lane+96] = e3*inv;
    }
}

// ============================================================================
// k_pr: att = P @ R.  grid (32, B) = (8 l-blks x 4 d-blks, B), 256 thr.
// ============================================================================
__global__ void __launch_bounds__(256) k_pr(const float* __restrict__ Rr)
{
    __shared__ __align__(16) float P[16*132];
    __shared__ __align__(16) float Rs[16*132];

    int blk = blockIdx.x, b = blockIdx.y;
    int l0 = (blk >> 2)*16, d0 = (blk & 3)*128;
    int t = threadIdx.x;

    #pragma unroll
    for (int i = 0; i < 8; i++){
        int f = i*256 + t; int r = f >> 7, c = f & 127;
        P[r*132 + c] = g_probs[(size_t)(b*LL + l0 + r)*LR + c];
    }

    int l = t >> 4, dq = t & 15;
    float4 acc0 = make_float4(0,0,0,0), acc1 = make_float4(0,0,0,0);
    for (int rc = 0; rc < 8; rc++){
        __syncthreads();
        {
            int r = t >> 4, c8 = (t & 15)*8;
            const float* src = Rr + (size_t)(b*LR + rc*16 + r)*D + d0 + c8;
            *(float4*)&Rs[r*132 + c8]     = *(const float4*)src;
            *(float4*)&Rs[r*132 + c8 + 4] = *(const float4*)(src + 4);
        }
        __syncthreads();
        #pragma unroll
        for (int r = 0; r < 16; r++){
            float p = P[l*132 + rc*16 + r];
            float4 v0 = *(const float4*)&Rs[r*132 + dq*8];
            float4 v1 = *(const float4*)&Rs[r*132 + dq*8 + 4];
            acc0.x = fmaf(p, v0.x, acc0.x); acc0.y = fmaf(p, v0.y, acc0.y);
            acc0.z = fmaf(p, v0.z, acc0.z); acc0.w = fmaf(p, v0.w, acc0.w);
            acc1.x = fmaf(p, v1.x, acc1.x); acc1.y = fmaf(p, v1.y, acc1.y);
            acc1.z = fmaf(p, v1.z, acc1.z); acc1.w = fmaf(p, v1.w, acc1.w);
        }
    }
    float* op = g_att + (size_t)(b*LL + l0 + l)*D + d0 + dq*8;
    *(float4*)op = acc0; *(float4*)(op + 4) = acc1;
}

// ============================================================================
// k_nrt: inv right norms, grid 512 (one warp per row)
// ============================================================================
__global__ void k_nrt(const float* __restrict__ Rr)
{
    int blk = blockIdx.x;
    int b = blk >> 4, r = (blk & 15)*8 + (threadIdx.x >> 5);
    int lane = threadIdx.x & 31;
    const float* row = Rr + (size_t)(b*LR + r) * D;
    float s = 0.f;
    #pragma unroll 4
    for (int i = lane; i < D; i += 32){ float v = row[i]; s = fmaf(v, v, s); }
    #pragma unroll
    for (int off = 16; off; off >>= 1) s += __shfl_xor_sync(0xffffffffu, s, off);
    if (!lane) g_invnrt[b*LR + r] = rsqrtf(fmaxf(s, 1e-6f));
}

// ============================================================================
// k_idx: argmax_r cosine(L[l], R[r]).  block = 32 l x 128 r, grid (4, B).
// ============================================================================
__global__ void __launch_bounds__(256) k_idx(
    const float* __restrict__ Lr, const float* __restrict__ Rr)
{
    __shared__ float Ls[16*36];
    __shared__ float Rs[16*132];
    __shared__ float sn[128];
    __shared__ float redv[32*17];
    __shared__ int   redi[32*17];

    int b = blockIdx.y, l0 = blockIdx.x*32, t = threadIdx.x;
    if (t < 128) sn[t] = g_invnrt[b*LR + t];

    int ly = t >> 4, tx = t & 15;
    float acc[2][8];
    #pragma unroll
    for (int i = 0; i < 2; i++)
        #pragma unroll
        for (int j = 0; j < 8; j++) acc[i][j] = 0.f;

    const float* Lb = Lr + (size_t)(b*LL + l0) * D;
    const float* Rb = Rr + ((size_t)b << 16);

    for (int kc = 0; kc < 32; kc++){
        __syncthreads();
        {
            int row = t >> 3, c2 = (t & 7)*2;
            float2 v = *(const float2*)(Lb + (size_t)row*D + kc*16 + c2);
            Ls[c2*36 + row] = v.x;
            Ls[(c2+1)*36 + row] = v.y;
        }
        {
            int row = t >> 1, c8 = (t & 1)*8;
            const float* src = Rb + (size_t)row*D + kc*16 + c8;
            float4 v0 = *(const float4*)src, v1 = *(const float4*)(src + 4);
            Rs[(c8+0)*132 + row] = v0.x; Rs[(c8+1)*132 + row] = v0.y;
            Rs[(c8+2)*132 + row] = v0.z; Rs[(c8+3)*132 + row] = v0.w;
            Rs[(c8+4)*132 + row] = v1.x; Rs[(c8+5)*132 + row] = v1.y;
            Rs[(c8+6)*132 + row] = v1.z; Rs[(c8+7)*132 + row] = v1.w;
        }
        __syncthreads();
        #pragma unroll
        for (int k = 0; k < 16; k++){
            float a0 = Ls[k*36 + ly], a1 = Ls[k*36 + ly + 16];
            float4 b0 = *(const float4*)&Rs[k*132 + tx*8];
            float4 b1 = *(const float4*)&Rs[k*132 + tx*8 + 4];
            float bv[8] = {b0.x,b0.y,b0.z,b0.w,b1.x,b1.y,b1.z,b1.w};
            #pragma unroll
            for (int j = 0; j < 8; j++){
                acc[0][j] = fmaf(a0, bv[j], acc[0][j]);
                acc[1][j] = fmaf(a1, bv[j], acc[1][j]);
            }
        }
    }
    #pragma unroll
    for (int i = 0; i < 2; i++){
        float bv = -1e30f; int bi = 0;
        #pragma unroll
        for (int j = 0; j < 8; j++){
            float v = acc[i][j] * sn[tx*8 + j];
            if (v > bv){ bv = v; bi = tx*8 + j; }
        }
        redv[(ly + i*16)*17 + tx] = bv;
        redi[(ly + i*16)*17 + tx] = bi;
    }
    __syncthreads();
    if (t < 32){
        float bv = -1e30f; int bi = 0;
        #pragma unroll
        for (int j = 0; j < 16; j++){
            float v = redv[t*17 + j];
            if (v > bv){ bv = v; bi = redi[t*17 + j]; }
        }
        g_idx[b*LL + l0 + t] = bi;
    }
}

// ============================================================================
// k_mp3: one mp_match epilogue (mode passed per launch).  grid 256.
// ============================================================================
__global__ void __launch_bounds__(256) k_mp3(
    const float* __restrict__ Lr, const float* __restrict__ hfw,
    const float* __restrict__ hbw, const float* __restrict__ Kmat,
    const float* __restrict__ Rr, float* __restrict__ out,
    int mode, int col0)
{
    __shared__ __align__(16) float P[16][68];
    __shared__ __align__(16) float Kc[64][68];
    __shared__ float hv[512];
    __shared__ float red[16][65];
    __shared__ int   sidx[16];

    int blk = blockIdx.x;
    int b = blk >> 3, l0 = (blk & 7) * 16;
    int t = threadIdx.x;

    if (mode == 0) { hv[t] = hfw[b*256 + t]; hv[256 + t] = hbw[b*256 + t]; }
    if (mode == 2 && t < 16) sidx[t] = g_idx[b*LL + l0 + t];

    int li = t >> 4, mj = t & 15;
    int srow = t >> 6, sk = t & 63;
    float cacc[4] = {0.f, 0.f, 0.f, 0.f};
    float acc[4]  = {0.f, 0.f, 0.f, 0.f};
    __syncthreads();

    for (int c = 0; c < 8; c++) {
        #pragma unroll
        for (int i = 0; i < 16; i++) {
            int f = i * 256 + t; int m = f >> 6, k = f & 63;
            Kc[m][k] = Kmat[(size_t)m * D + c*64 + k];
        }
        #pragma unroll
        for (int i = 0; i < 4; i++) {
            int row = i*4 + srow;
            int gl = b*LL + l0 + row;
            float lv = Lr[(size_t)gl * D + c*64 + sk];
            float av;
            if (mode == 0)      av = hv[c*64 + sk];
            else if (mode == 1) av = g_att[(size_t)gl * D + c*64 + sk];
            else                av = Rr[(size_t)(b*LR + sidx[row]) * D + c*64 + sk];
            float p = lv * av;
            P[row][sk] = p;
            cacc[i] += p;
        }
        __syncthreads();
        #pragma unroll
        for (int k4 = 0; k4 < 16; k4++) {
            float4 p4 = *(const float4*)&P[li][k4*4];
            #pragma unroll
            for (int j = 0; j < 4; j++) {
                float4 kv = *(const float4*)&Kc[j*16 + mj][k4*4];
                acc[j] = fmaf(p4.x, kv.x, fmaf(p4.y, kv.y, fmaf(p4.z, kv.z, fmaf(p4.w, kv.w, acc[j]))));
            }
        }
        __syncthreads();
    }
    #pragma unroll
    for (int i = 0; i < 4; i++) red[i*4 + srow][sk] = cacc[i];
    __syncthreads();
    if (t < 16) {
        float s = 0.f;
        #pragma unroll
        for (int k = 0; k < 64; k++) s += red[t][k];
        out[(size_t)(b*LL + l0 + t) * OC + col0] = tanhf(s);
    }
    #pragma unroll
    for (int j = 0; j < 4; j++)
        out[(size_t)(b*LL + l0 + li) * OC + col0 + 1 + j*16 + mj] = tanhf(acc[j]);
}

// ============================================================================
extern "C" void kernel_launch(void* const* d_in, const int* in_sizes, int n_in,
                              void* d_out, int out_size)
{
    const float* reps_lt = (const float*)d_in[0];
    const float* reps_rt = (const float*)d_in[3];
    const float* h_rt_fw = (const float*)d_in[4];
    const float* h_rt_bw = (const float*)d_in[5];
    const float* k_full  = (const float*)d_in[6];
    const float* k_mpW   = (const float*)d_in[7];
    const float* attn_w1 = (const float*)d_in[8];
    const float* diag_w  = (const float*)d_in[9];
    const float* k_attW  = (const float*)d_in[10];
    const float* k_maxW  = (const float*)d_in[11];
    float* out = (float*)d_out;

    static cudaStream_t s2 = 0, s3 = 0;
    static cudaEvent_t  eF = 0, eJ2 = 0, eJ3 = 0;
    if (!s2) {
        cudaFuncSetAttribute(k_mpool_mma, cudaFuncAttributeMaxDynamicSharedMemorySize, 83968);
        cudaStreamCreateWithFlags(&s2, cudaStreamNonBlocking);
        cudaStreamCreateWithFlags(&s3, cudaStreamNonBlocking);
        cudaEventCreateWithFlags(&eF,  cudaEventDisableTiming);
        cudaEventCreateWithFlags(&eJ2, cudaEventDisableTiming);
        cudaEventCreateWithFlags(&eJ3, cudaEventDisableTiming);
    }

    // fork side streams off the (captured) main stream
    cudaEventRecord(eF, 0);
    cudaStreamWaitEvent(s2, eF, 0);
    cudaStreamWaitEvent(s3, eF, 0);

    // main stream: tensor-core chain (cols 65..128 via g_mx + k_comb)
    k_split<<<dim3(8, B), 256>>>(reps_lt);
    k_mpool_mma<<<dim3(128, B), 256, 83968>>>(reps_rt, k_mpW);
    k_comb<<<1024, 256>>>(out);

    // s2: attentive path -> mp3 mode1 (cols 129..193)
    k_algt<<<(B*LL + B*LR)/16, 256, 0, s2>>>(reps_lt, reps_rt, attn_w1, diag_w);
    k_score<<<dim3(8, B), 256, 0, s2>>>();
    k_pr<<<dim3(32, B), 256, 0, s2>>>(reps_rt);
    k_mp3<<<256, 256, 0, s2>>>(reps_lt, h_rt_fw, h_rt_bw, k_attW, reps_rt, out, 1, 129);

    // s3: full match (cols 0..64) + max-attentive path -> mp3 mode2 (cols 194..258)
    k_mp3<<<256, 256, 0, s3>>>(reps_lt, h_rt_fw, h_rt_bw, k_full, reps_rt, out, 0, 0);
    k_nrt<<<512, 256, 0, s3>>>(reps_rt);
    k_idx<<<dim3(4, B), 256, 0, s3>>>(reps_lt, reps_rt);
    k_mp3<<<256, 256, 0, s3>>>(reps_lt, h_rt_fw, h_rt_bw, k_maxW, reps_rt, out, 2, 194);

    // join side streams back into the main stream
    cudaEventRecord(eJ2, s2);
    cudaEventRecord(eJ3, s3);
    cudaStreamWaitEvent(0, eJ2, 0);
    cudaStreamWaitEvent(0, eJ3, 0);
}

// round 10
// speedup vs baseline: 1.1063x; 1.1063x over previous
#include <cuda_runtime.h>
#include <math.h>
#include <stdint.h>

#define B   32
#define LL  128
#define LR  128
#define D   512
#define A   128
#define OC  259   // 1+64 | 64 | 1+64 | 1+64

// ---- scratch (static device globals; no runtime allocation) ----
__device__ float g_algt[(B*LL + B*LR) * A];
__device__ float g_att[B*LL*D];
__device__ float g_probs[B*LL*LR];
__device__ float g_invnrt[B*LR];
__device__ int   g_idx[B*LL];
// pre-split bf16 hi/lo swizzled tiles: (b,chunk) tiles of 128 rows x 128B
__device__ __align__(16) unsigned char g_Lh[B*8*16384];
__device__ __align__(16) unsigned char g_Ll[B*8*16384];
__device__ __align__(16) unsigned char g_Rh[B*8*16384];
__device__ __align__(16) unsigned char g_Rl[B*8*16384];
// W1 transposed to B-operand tiles: 8 chunks x (128 a-rows x 64 d) hi/lo
__device__ __align__(16) unsigned char g_Wh[8*16384];
__device__ __align__(16) unsigned char g_Wl[8*16384];

__device__ __forceinline__ uint32_t swz(uint32_t x){ return x ^ ((x >> 3) & 0x70u); }
__device__ __forceinline__ uint32_t smem_u32(const void* p){
    uint32_t a;
    asm("{ .reg .u64 t; cvta.to.shared.u64 t, %1; cvt.u32.u64 %0, t; }" : "=r"(a) : "l"(p));
    return a;
}
__device__ __forceinline__ void split2(float x0, float x1, uint32_t& h, uint32_t& l){
    asm("cvt.rn.bf16x2.f32 %0, %1, %2;" : "=r"(h) : "f"(x1), "f"(x0));
    float h0 = __uint_as_float(h << 16), h1 = __uint_as_float(h & 0xffff0000u);
    asm("cvt.rn.bf16x2.f32 %0, %1, %2;" : "=r"(l) : "f"(x1 - h1), "f"(x0 - h0));
}

#define LDSM4(r0,r1,r2,r3,addr) \
    asm volatile("ldmatrix.sync.aligned.m8n8.x4.shared.b16 {%0,%1,%2,%3}, [%4];" \
        : "=r"(r0),"=r"(r1),"=r"(r2),"=r"(r3) : "r"(addr))
#define CP16(s,g) \
    asm volatile("cp.async.cg.shared.global [%0], [%1], 16;" :: "r"(s), "l"(g))
#define CPCOMMIT() asm volatile("cp.async.commit_group;")
#define CPWAIT1()  asm volatile("cp.async.wait_group 1;")
#define CPWAIT0()  asm volatile("cp.async.wait_group 0;")

__device__ __forceinline__ void mma_bf16(float* d, const uint32_t* a, const uint32_t* b){
    asm volatile("mma.sync.aligned.m16n8k16.row.col.f32.bf16.bf16.f32 "
        "{%0,%1,%2,%3}, {%4,%5,%6,%7}, {%8,%9}, {%0,%1,%2,%3};"
        : "+f"(d[0]),"+f"(d[1]),"+f"(d[2]),"+f"(d[3])
        : "r"(a[0]),"r"(a[1]),"r"(a[2]),"r"(a[3]), "r"(b[0]),"r"(b[1]));
}

// ============================================================================
// k_split: X (fp32, [b][row][512]) -> hi/lo bf16 swizzled tiles. grid (8, B).
// which = 0 -> g_Lh/g_Ll, 1 -> g_Rh/g_Rl
// ============================================================================
__global__ void __launch_bounds__(256) k_split(const float* __restrict__ X, int which)
{
    int c = blockIdx.x, b = blockIdx.y, t = threadIdx.x;
    const float* Xb = X + ((size_t)b << 16) + c*64;
    size_t tile = ((size_t)(b*8 + c)) << 14;
    unsigned char* dh = (which ? g_Rh : g_Lh) + tile;
    unsigned char* dl = (which ? g_Rl : g_Ll) + tile;
    #pragma unroll
    for (int i = 0; i < 4; i++){
        int f = i*256 + t; int row = f >> 3, q = f & 7;
        const float* src = Xb + (size_t)row*512 + q*8;
        float4 v0 = *(const float4*)src, v1 = *(const float4*)(src + 4);
        uint32_t h01,l01,h23,l23,h45,l45,h67,l67;
        split2(v0.x, v0.y, h01, l01);
        split2(v0.z, v0.w, h23, l23);
        split2(v1.x, v1.y, h45, l45);
        split2(v1.z, v1.w, h67, l67);
        uint32_t off = swz((uint32_t)(row*128 + q*16));
        *(uint4*)(dh + off) = make_uint4(h01, h23, h45, h67);
        *(uint4*)(dl + off) = make_uint4(l01, l23, l45, l67);
    }
}

// ============================================================================
// k_splitW: W1 [d=512][a=128] -> transposed B tiles (rows=a, k=d). grid (8).
// ============================================================================
__global__ void __launch_bounds__(256) k_splitW(const float* __restrict__ W1)
{
    int c = blockIdx.x, t = threadIdx.x;
    size_t tile = ((size_t)c) << 14;
    #pragma unroll
    for (int i = 0; i < 8; i++){
        int f = i*256 + t; int row = f >> 4, q = f & 15;   // row = a, q -> d group
        int d0 = c*64 + q*4;
        float w0 = W1[(size_t)(d0+0)*A + row];
        float w1 = W1[(size_t)(d0+1)*A + row];
        float w2 = W1[(size_t)(d0+2)*A + row];
        float w3 = W1[(size_t)(d0+3)*A + row];
        uint32_t h01,l01,h23,l23;
        split2(w0, w1, h01, l01);
        split2(w2, w3, h23, l23);
        uint32_t off = swz((uint32_t)(row*128 + q*8));
        *(uint2*)(g_Wh + tile + off) = make_uint2(h01, h23);
        *(uint2*)(g_Wl + tile + off) = make_uint2(l01, l23);
    }
}

// ============================================================================
// k_mpool_mma (R8 version): CTA = (m, b).  C[l,r] = sum_d L[l,d]*(R[r,d]*K_m[d]).
// out[b,l,65+m] = tanh(max_r C).  dyn smem 100352 B, occ 2.
// ============================================================================
__global__ void __launch_bounds__(256, 2) k_mpool_mma(
    const float* __restrict__ Rr, const float* __restrict__ Kmp,
    float* __restrict__ out)
{
    extern __shared__ __align__(16) unsigned char dyn[];
    int m = blockIdx.x, b = blockIdx.y;
    int t = threadIdx.x, wid = t >> 5, lane = t & 31;
    uint32_t base = smem_u32(dyn);
    uint32_t Abuf[2] = {base, base + 32768};
    uint32_t Bh = base + 65536, Bl = base + 81920;
    float* sK = (float*)(dyn + 98304);
    for (int i = t; i < 512; i += 256) sK[i] = Kmp[(size_t)m*512 + i];

    {
        const unsigned char* gh = g_Lh + (((size_t)(b*8)) << 14);
        const unsigned char* gl = g_Ll + (((size_t)(b*8)) << 14);
        #pragma unroll
        for (int i = 0; i < 4; i++){
            uint32_t o = (uint32_t)(i*256 + t) * 16;
            CP16(Abuf[0] + o, gh + o);
            CP16(Abuf[0] + 16384 + o, gl + o);
        }
        CPCOMMIT();
    }
    __syncthreads();

    int wl = wid >> 2, wn = wid & 3;
    float acc[4][4][4];
    #pragma unroll
    for (int i = 0; i < 4; i++)
        #pragma unroll
        for (int j = 0; j < 4; j++)
            #pragma unroll
            for (int k = 0; k < 4; k++) acc[i][j][k] = 0.f;

    int rowA = lane & 15;
    int cbA  = lane >> 4;
    int rowB = ((lane >> 4) & 1) * 8 + (lane & 7);
    int cbB  = (lane >> 3) & 1;

    const float* Rb = Rr + ((size_t)b << 16);
    int rrow = t >> 3, rq = t & 7;

    for (int c = 0; c < 8; c++){
        if (c < 7){
            uint32_t nb = Abuf[(c+1) & 1];
            const unsigned char* gh = g_Lh + (((size_t)(b*8 + c+1)) << 14);
            const unsigned char* gl = g_Ll + (((size_t)(b*8 + c+1)) << 14);
            #pragma unroll
            for (int i = 0; i < 4; i++){
                uint32_t o = (uint32_t)(i*256 + t) * 16;
                CP16(nb + o, gh + o);
                CP16(nb + 16384 + o, gl + o);
            }
            CPCOMMIT();
        }
        {
            float4 k0 = *(const float4*)(sK + c*64 + rq*8);
            float4 k1 = *(const float4*)(sK + c*64 + rq*8 + 4);
            #pragma unroll
            for (int i = 0; i < 4; i++){
                int row = rrow + i*32;
                const float* src = Rb + (size_t)row*512 + c*64 + rq*8;
                float4 r0 = *(const float4*)src, r1 = *(const float4*)(src + 4);
                uint32_t h01,l01,h23,l23,h45,l45,h67,l67;
                split2(r0.x*k0.x, r0.y*k0.y, h01, l01);
                split2(r0.z*k0.z, r0.w*k0.w, h23, l23);
                split2(r1.x*k1.x, r1.y*k1.y, h45, l45);
                split2(r1.z*k1.z, r1.w*k1.w, h67, l67);
                uint32_t off = swz((uint32_t)(row*128 + rq*16));
                asm volatile("st.shared.v4.b32 [%0], {%1,%2,%3,%4};"
                             :: "r"(Bh+off), "r"(h01), "r"(h23), "r"(h45), "r"(h67));
                asm volatile("st.shared.v4.b32 [%0], {%1,%2,%3,%4};"
                             :: "r"(Bl+off), "r"(l01), "r"(l23), "r"(l45), "r"(l67));
            }
        }
        if (c < 7) { CPWAIT1(); } else { CPWAIT0(); }
        __syncthreads();

        uint32_t Ah = Abuf[c & 1], Al = Ah + 16384;
        #pragma unroll
        for (int ks = 0; ks < 4; ks++){
            uint32_t aoffs[4], boffs[2];
            #pragma unroll
            for (int mt = 0; mt < 4; mt++)
                aoffs[mt] = swz((uint32_t)((wl*64 + mt*16 + rowA)*128 + ks*32 + cbA*16));
            #pragma unroll
            for (int jp = 0; jp < 2; jp++)
                boffs[jp] = swz((uint32_t)((wn*32 + jp*16 + rowB)*128 + ks*32 + cbB*16));

            uint32_t bh_[4][2];
            #pragma unroll
            for (int jp = 0; jp < 2; jp++)
                LDSM4(bh_[jp*2][0], bh_[jp*2][1], bh_[jp*2+1][0], bh_[jp*2+1][1], Bh + boffs[jp]);
            {
                uint32_t al_[4][4];
                #pragma unroll
                for (int mt = 0; mt < 4; mt++)
                    LDSM4(al_[mt][0], al_[mt][1], al_[mt][2], al_[mt][3], Al + aoffs[mt]);
                #pragma unroll
                for (int mt = 0; mt < 4; mt++)
                    #pragma unroll
                    for (int nt = 0; nt < 4; nt++)
                        mma_bf16(acc[mt][nt], al_[mt], bh_[nt]);
            }
            uint32_t ah_[4][4];
            #pragma unroll
            for (int mt = 0; mt < 4; mt++)
                LDSM4(ah_[mt][0], ah_[mt][1], ah_[mt][2], ah_[mt][3], Ah + aoffs[mt]);
            #pragma unroll
            for (int mt = 0; mt < 4; mt++)
                #pragma unroll
                for (int nt = 0; nt < 4; nt++)
                    mma_bf16(acc[mt][nt], ah_[mt], bh_[nt]);
            {
                uint32_t bl_[4][2];
                #pragma unroll
                for (int jp = 0; jp < 2; jp++)
                    LDSM4(bl_[jp*2][0], bl_[jp*2][1], bl_[jp*2+1][0], bl_[jp*2+1][1], Bl + boffs[jp]);
                #pragma unroll
                for (int mt = 0; mt < 4; mt++)
                    #pragma unroll
                    for (int nt = 0; nt < 4; nt++)
                        mma_bf16(acc[mt][nt], ah_[mt], bl_[nt]);
            }
        }
        __syncthreads();
    }

    float* red = (float*)dyn;
    int g = lane >> 2, tg = lane & 3;
    #pragma unroll
    for (int mt = 0; mt < 4; mt++){
        float m0 = -1e30f, m1 = -1e30f;
        #pragma unroll
        for (int nt = 0; nt < 4; nt++){
            m0 = fmaxf(m0, fmaxf(acc[mt][nt][0], acc[mt][nt][1]));
            m1 = fmaxf(m1, fmaxf(acc[mt][nt][2], acc[mt][nt][3]));
        }
        m0 = fmaxf(m0, __shfl_xor_sync(0xffffffffu, m0, 1));
        m0 = fmaxf(m0, __shfl_xor_sync(0xffffffffu, m0, 2));
        m1 = fmaxf(m1, __shfl_xor_sync(0xffffffffu, m1, 1));
        m1 = fmaxf(m1, __shfl_xor_sync(0xffffffffu, m1, 2));
        if (tg == 0){
            red[(wl*64 + mt*16 + g)*4 + wn]     = m0;
            red[(wl*64 + mt*16 + g + 8)*4 + wn] = m1;
        }
    }
    __syncthreads();
    if (t < 128){
        float v = fmaxf(fmaxf(red[t*4], red[t*4+1]), fmaxf(red[t*4+2], red[t*4+3]));
        out[((size_t)(b*LL + t))*OC + 65 + m] = tanhf(v);
    }
}

// ============================================================================
// k_algt_mma: tanh([L;R] @ W1) (*diag for L rows) via 3-term split bf16 MMA.
// grid 64 (32 L-blocks then 32 R-blocks), 256 thr.
// dyn smem: buf[2] x (Ah 16K | Al 16K | Wh 16K | Wl 16K) = 131072 B
// ============================================================================
__global__ void __launch_bounds__(256) k_algt_mma(const float* __restrict__ diag)
{
    extern __shared__ __align__(16) unsigned char dyn[];
    __shared__ float sdiag[128];
    int bi = blockIdx.x;
    int isL = (bi < 32) ? 1 : 0;
    int b = isL ? bi : bi - 32;
    int t = threadIdx.x, wid = t >> 5, lane = t & 31;
    uint32_t base = smem_u32(dyn);
    uint32_t buf[2] = {base, base + 65536};

    if (t < 128) sdiag[t] = diag[t];

    const unsigned char* srcH = isL ? g_Lh : g_Rh;
    const unsigned char* srcL = isL ? g_Ll : g_Rl;

    // preload chunk 0: A hi/lo + W hi/lo
    {
        const unsigned char* ah = srcH + (((size_t)(b*8)) << 14);
        const unsigned char* al = srcL + (((size_t)(b*8)) << 14);
        #pragma unroll
        for (int i = 0; i < 4; i++){
            uint32_t o = (uint32_t)(i*256 + t) * 16;
            CP16(buf[0] + o,         ah + o);
            CP16(buf[0] + 16384 + o, al + o);
            CP16(buf[0] + 32768 + o, g_Wh + o);
            CP16(buf[0] + 49152 + o, g_Wl + o);
        }
        CPCOMMIT();
    }

    int wl = wid >> 2, wn = wid & 3;
    float acc[4][4][4];
    #pragma unroll
    for (int i = 0; i < 4; i++)
        #pragma unroll
        for (int j = 0; j < 4; j++)
            #pragma unroll
            for (int k = 0; k < 4; k++) acc[i][j][k] = 0.f;

    int rowA = lane & 15;
    int cbA  = lane >> 4;
    int rowB = ((lane >> 4) & 1) * 8 + (lane & 7);
    int cbB  = (lane >> 3) & 1;

    for (int c = 0; c < 8; c++){
        if (c < 7){
            uint32_t nb = buf[(c+1) & 1];
            const unsigned char* ah = srcH + (((size_t)(b*8 + c+1)) << 14);
            const unsigned char* al = srcL + (((size_t)(b*8 + c+1)) << 14);
            const unsigned char* wh = g_Wh + (((size_t)(c+1)) << 14);
            const unsigned char* wlp = g_Wl + (((size_t)(c+1)) << 14);
            #pragma unroll
            for (int i = 0; i < 4; i++){
                uint32_t o = (uint32_t)(i*256 + t) * 16;
                CP16(nb + o,         ah + o);
                CP16(nb + 16384 + o, al + o);
                CP16(nb + 32768 + o, wh + o);
                CP16(nb + 49152 + o, wlp + o);
            }
            CPCOMMIT();
        }
        if (c < 7) { CPWAIT1(); } else { CPWAIT0(); }
        __syncthreads();

        uint32_t Ah = buf[c & 1], Al = Ah + 16384, Wh = Ah + 32768, Wlb = Ah + 49152;
        #pragma unroll
        for (int ks = 0; ks < 4; ks++){
            uint32_t aoffs[4], boffs[2];
            #pragma unroll
            for (int mt = 0; mt < 4; mt++)
                aoffs[mt] = swz((uint32_t)((wl*64 + mt*16 + rowA)*128 + ks*32 + cbA*16));
            #pragma unroll
            for (int jp = 0; jp < 2; jp++)
                boffs[jp] = swz((uint32_t)((wn*32 + jp*16 + rowB)*128 + ks*32 + cbB*16));

            uint32_t bh_[4][2];
            #pragma unroll
            for (int jp = 0; jp < 2; jp++)
                LDSM4(bh_[jp*2][0], bh_[jp*2][1], bh_[jp*2+1][0], bh_[jp*2+1][1], Wh + boffs[jp]);
            {
                uint32_t al_[4][4];
                #pragma unroll
                for (int mt = 0; mt < 4; mt++)
                    LDSM4(al_[mt][0], al_[mt][1], al_[mt][2], al_[mt][3], Al + aoffs[mt]);
                #pragma unroll
                for (int mt = 0; mt < 4; mt++)
                    #pragma unroll
                    for (int nt = 0; nt < 4; nt++)
                        mma_bf16(acc[mt][nt], al_[mt], bh_[nt]);
            }
            uint32_t ah_[4][4];
            #pragma unroll
            for (int mt = 0; mt < 4; mt++)
                LDSM4(ah_[mt][0], ah_[mt][1], ah_[mt][2], ah_[mt][3], Ah + aoffs[mt]);
            #pragma unroll
            for (int mt = 0; mt < 4; mt++)
                #pragma unroll
                for (int nt = 0; nt < 4; nt++)
                    mma_bf16(acc[mt][nt], ah_[mt], bh_[nt]);
            {
                uint32_t bl_[4][2];
                #pragma unroll
                for (int jp = 0; jp < 2; jp++)
                    LDSM4(bl_[jp*2][0], bl_[jp*2][1], bl_[jp*2+1][0], bl_[jp*2+1][1], Wlb + boffs[jp]);
                #pragma unroll
                for (int mt = 0; mt < 4; mt++)
                    #pragma unroll
                    for (int nt = 0; nt < 4; nt++)
                        mma_bf16(acc[mt][nt], ah_[mt], bl_[nt]);
            }
        }
        __syncthreads();
    }

    // epilogue: tanh (+diag for L rows), write g_algt fp32
    int g = lane >> 2, tg = lane & 3;
    size_t rbase = (size_t)bi * 128;
    #pragma unroll
    for (int mt = 0; mt < 4; mt++){
        int r0 = wl*64 + mt*16 + g, r1 = r0 + 8;
        #pragma unroll
        for (int nt = 0; nt < 4; nt++){
            int col = wn*32 + nt*8 + tg*2;
            float d0 = isL ? sdiag[col] : 1.f;
            float d1 = isL ? sdiag[col+1] : 1.f;
            float2 v0 = make_float2(tanhf(acc[mt][nt][0])*d0, tanhf(acc[mt][nt][1])*d1);
            float2 v1 = make_float2(tanhf(acc[mt][nt][2])*d0, tanhf(acc[mt][nt][3])*d1);
            *(float2*)&g_algt[(rbase + r0)*A + col] = v0;
            *(float2*)&g_algt[(rbase + r1)*A + col] = v1;
        }
    }
}

// ============================================================================
// k_score: per block (b, 16 l's): scores -> softmax -> g_probs. grid (8, B).
// ============================================================================
__global__ void __launch_bounds__(256) k_score()
{
    __shared__ float alt[16][129];
    __shared__ float art[16][129];
    __shared__ float S[16][132];

    int b  = blockIdx.y;
    int l0 = blockIdx.x * 16;
    int t  = threadIdx.x;
    int li = t >> 4, rj = t & 15;

    #pragma unroll
    for (int i = 0; i < 8; i++) {
        int f = i * 256 + t;
        int r = f >> 7, a = f & 127;
        alt[r][a] = g_algt[(size_t)(b*LL + l0 + r) * A + a];
    }

    for (int rc = 0; rc < 8; rc++) {
        __syncthreads();
        #pragma unroll
        for (int i = 0; i < 8; i++) {
            int f = i * 256 + t;
            int r = f >> 7, a = f & 127;
            art[r][a] = g_algt[(size_t)(B*LL + b*LR + rc*16 + r) * A + a];
        }
        __syncthreads();
        float s = 0.f;
        #pragma unroll 4
        for (int a = 0; a < A; a++) s = fmaf(alt[li][a], art[rj][a], s);
        S[li][rc*16 + rj] = s;
    }
    __syncthreads();

    int w = t >> 5, lane = t & 31;
    #pragma unroll
    for (int rr = w*2; rr < w*2 + 2; rr++) {
        float v0 = S[rr][lane], v1 = S[rr][lane+32],
              v2 = S[rr][lane+64], v3 = S[rr][lane+96];
        float m0 = fmaxf(fmaxf(v0,v1), fmaxf(v2,v3));
        #pragma unroll
        for (int off = 16; off; off >>= 1) m0 = fmaxf(m0, __shfl_xor_sync(0xffffffffu, m0, off));
        float e0 = expf(v0-m0), e1 = expf(v1-m0), e2 = expf(v2-m0), e3 = expf(v3-m0);
        float sum = e0+e1+e2+e3;
        #pragma unroll
        for (int off = 16; off; off >>= 1) sum += __shfl_xor_sync(0xffffffffu, sum, off);
        float inv = 1.f / sum;
        float* pp = g_probs + (size_t)(b*LL + l0 + rr)*LR;
        pp[lane] = e0*inv; pp[lane+32] = e1*inv;
        pp[lane+64] = e2*inv; pp[lane+96] = e3*inv;
    }
}

// ============================================================================
// k_pr: att = P @ R.  grid (32, B), 256 thr.
// ============================================================================
__global__ void __launch_bounds__(256) k_pr(const float* __restrict__ Rr)
{
    __shared__ __align__(16) float P[16*132];
    __shared__ __align__(16) float Rs[16*132];

    int blk = blockIdx.x, b = blockIdx.y;
    int l0 = (blk >> 2)*16, d0 = (blk & 3)*128;
    int t = threadIdx.x;

    #pragma unroll
    for (int i = 0; i < 8; i++){
        int f = i*256 + t; int r = f >> 7, c = f & 127;
        P[r*132 + c] = g_probs[(size_t)(b*LL + l0 + r)*LR + c];
    }

    int l = t >> 4, dq = t & 15;
    float4 acc0 = make_float4(0,0,0,0), acc1 = make_float4(0,0,0,0);
    for (int rc = 0; rc < 8; rc++){
        __syncthreads();
        {
            int r = t >> 4, c8 = (t & 15)*8;
            const float* src = Rr + (size_t)(b*LR + rc*16 + r)*D + d0 + c8;
            *(float4*)&Rs[r*132 + c8]     = *(const float4*)src;
            *(float4*)&Rs[r*132 + c8 + 4] = *(const float4*)(src + 4);
        }
        __syncthreads();
        #pragma unroll
        for (int r = 0; r < 16; r++){
            float p = P[l*132 + rc*16 + r];
            float4 v0 = *(const float4*)&Rs[r*132 + dq*8];
            float4 v1 = *(const float4*)&Rs[r*132 + dq*8 + 4];
            acc0.x = fmaf(p, v0.x, acc0.x); acc0.y = fmaf(p, v0.y, acc0.y);
            acc0.z = fmaf(p, v0.z, acc0.z); acc0.w = fmaf(p, v0.w, acc0.w);
            acc1.x = fmaf(p, v1.x, acc1.x); acc1.y = fmaf(p, v1.y, acc1.y);
            acc1.z = fmaf(p, v1.z, acc1.z); acc1.w = fmaf(p, v1.w, acc1.w);
        }
    }
    float* op = g_att + (size_t)(b*LL + l0 + l)*D + d0 + dq*8;
    *(float4*)op = acc0; *(float4*)(op + 4) = acc1;
}

// ============================================================================
// k_nrt: inv right norms, grid 512 (one warp per row)
// ============================================================================
__global__ void k_nrt(const float* __restrict__ Rr)
{
    int blk = blockIdx.x;
    int b = blk >> 4, r = (blk & 15)*8 + (threadIdx.x >> 5);
    int lane = threadIdx.x & 31;
    const float* row = Rr + (size_t)(b*LR + r) * D;
    float s = 0.f;
    #pragma unroll 4
    for (int i = lane; i < D; i += 32){ float v = row[i]; s = fmaf(v, v, s); }
    #pragma unroll
    for (int off = 16; off; off >>= 1) s += __shfl_xor_sync(0xffffffffu, s, off);
    if (!lane) g_invnrt[b*LR + r] = rsqrtf(fmaxf(s, 1e-6f));
}

// ============================================================================
// k_idx: argmax_r cosine(L[l], R[r]).  block = 32 l x 128 r, grid (4, B).
// ============================================================================
__global__ void __launch_bounds__(256) k_idx(
    const float* __restrict__ Lr, const float* __restrict__ Rr)
{
    __shared__ float Ls[16*36];
    __shared__ float Rs[16*132];
    __shared__ float sn[128];
    __shared__ float redv[32*17];
    __shared__ int   redi[32*17];

    int b = blockIdx.y, l0 = blockIdx.x*32, t = threadIdx.x;
    if (t < 128) sn[t] = g_invnrt[b*LR + t];

    int ly = t >> 4, tx = t & 15;
    float acc[2][8];
    #pragma unroll
    for (int i = 0; i < 2; i++)
        #pragma unroll
        for (int j = 0; j < 8; j++) acc[i][j] = 0.f;

    const float* Lb = Lr + (size_t)(b*LL + l0) * D;
    const float* Rb = Rr + ((size_t)b << 16);

    for (int kc = 0; kc < 32; kc++){
        __syncthreads();
        {
            int row = t >> 3, c2 = (t & 7)*2;
            float2 v = *(const float2*)(Lb + (size_t)row*D + kc*16 + c2);
            Ls[c2*36 + row] = v.x;
            Ls[(c2+1)*36 + row] = v.y;
        }
        {
            int row = t >> 1, c8 = (t & 1)*8;
            const float* src = Rb + (size_t)row*D + kc*16 + c8;
            float4 v0 = *(const float4*)src, v1 = *(const float4*)(src + 4);
            Rs[(c8+0)*132 + row] = v0.x; Rs[(c8+1)*132 + row] = v0.y;
            Rs[(c8+2)*132 + row] = v0.z; Rs[(c8+3)*132 + row] = v0.w;
            Rs[(c8+4)*132 + row] = v1.x; Rs[(c8+5)*132 + row] = v1.y;
            Rs[(c8+6)*132 + row] = v1.z; Rs[(c8+7)*132 + row] = v1.w;
        }
        __syncthreads();
        #pragma unroll
        for (int k = 0; k < 16; k++){
            float a0 = Ls[k*36 + ly], a1 = Ls[k*36 + ly + 16];
            float4 b0 = *(const float4*)&Rs[k*132 + tx*8];
            float4 b1 = *(const float4*)&Rs[k*132 + tx*8 + 4];
            float bv[8] = {b0.x,b0.y,b0.z,b0.w,b1.x,b1.y,b1.z,b1.w};
            #pragma unroll
            for (int j = 0; j < 8; j++){
                acc[0][j] = fmaf(a0, bv[j], acc[0][j]);
                acc[1][j] = fmaf(a1, bv[j], acc[1][j]);
            }
        }
    }
    #pragma unroll
    for (int i = 0; i < 2; i++){
        float bv = -1e30f; int bi = 0;
        #pragma unroll
        for (int j = 0; j < 8; j++){
            float v = acc[i][j] * sn[tx*8 + j];
            if (v > bv){ bv = v; bi = tx*8 + j; }
        }
        redv[(ly + i*16)*17 + tx] = bv;
        redi[(ly + i*16)*17 + tx] = bi;
    }
    __syncthreads();
    if (t < 32){
        float bv = -1e30f; int bi = 0;
        #pragma unroll
        for (int j = 0; j < 16; j++){
            float v = redv[t*17 + j];
            if (v > bv){ bv = v; bi = redi[t*17 + j]; }
        }
        g_idx[b*LL + l0 + t] = bi;
    }
}

// ============================================================================
// k_mp3: one mp_match epilogue (mode per launch).  grid 256.
// ============================================================================
__global__ void __launch_bounds__(256) k_mp3(
    const float* __restrict__ Lr, const float* __restrict__ hfw,
    const float* __restrict__ hbw, const float* __restrict__ Kmat,
    const float* __restrict__ Rr, float* __restrict__ out,
    int mode, int col0)
{
    __shared__ __align__(16) float P[16][68];
    __shared__ __align__(16) float Kc[64][68];
    __shared__ float hv[512];
    __shared__ float red[16][65];
    __shared__ int   sidx[16];

    int blk = blockIdx.x;
    int b = blk >> 3, l0 = (blk & 7) * 16;
    int t = threadIdx.x;

    if (mode == 0) { hv[t] = hfw[b*256 + t]; hv[256 + t] = hbw[b*256 + t]; }
    if (mode == 2 && t < 16) sidx[t] = g_idx[b*LL + l0 + t];

    int li = t >> 4, mj = t & 15;
    int srow = t >> 6, sk = t & 63;
    float cacc[4] = {0.f, 0.f, 0.f, 0.f};
    float acc[4]  = {0.f, 0.f, 0.f, 0.f};
    __syncthreads();

    for (int c = 0; c < 8; c++) {
        #pragma unroll
        for (int i = 0; i < 16; i++) {
            int f = i * 256 + t; int m = f >> 6, k = f & 63;
            Kc[m][k] = Kmat[(size_t)m * D + c*64 + k];
        }
        #pragma unroll
        for (int i = 0; i < 4; i++) {
            int row = i*4 + srow;
            int gl = b*LL + l0 + row;
            float lv = Lr[(size_t)gl * D + c*64 + sk];
            float av;
            if (mode == 0)      av = hv[c*64 + sk];
            else if (mode == 1) av = g_att[(size_t)gl * D + c*64 + sk];
            else                av = Rr[(size_t)(b*LR + sidx[row]) * D + c*64 + sk];
            float p = lv * av;
            P[row][sk] = p;
            cacc[i] += p;
        }
        __syncthreads();
        #pragma unroll
        for (int k4 = 0; k4 < 16; k4++) {
            float4 p4 = *(const float4*)&P[li][k4*4];
            #pragma unroll
            for (int j = 0; j < 4; j++) {
                float4 kv = *(const float4*)&Kc[j*16 + mj][k4*4];
                acc[j] = fmaf(p4.x, kv.x, fmaf(p4.y, kv.y, fmaf(p4.z, kv.z, fmaf(p4.w, kv.w, acc[j]))));
            }
        }
        __syncthreads();
    }
    #pragma unroll
    for (int i = 0; i < 4; i++) red[i*4 + srow][sk] = cacc[i];
    __syncthreads();
    if (t < 16) {
        float s = 0.f;
        #pragma unroll
        for (int k = 0; k < 64; k++) s += red[t][k];
        out[(size_t)(b*LL + l0 + t) * OC + col0] = tanhf(s);
    }
    #pragma unroll
    for (int j = 0; j < 4; j++)
        out[(size_t)(b*LL + l0 + li) * OC + col0 + 1 + j*16 + mj] = tanhf(acc[j]);
}

// ============================================================================
extern "C" void kernel_launch(void* const* d_in, const int* in_sizes, int n_in,
                              void* d_out, int out_size)
{
    const float* reps_lt = (const float*)d_in[0];
    const float* reps_rt = (const float*)d_in[3];
    const float* h_rt_fw = (const float*)d_in[4];
    const float* h_rt_bw = (const float*)d_in[5];
    const float* k_full  = (const float*)d_in[6];
    const float* k_mpW   = (const float*)d_in[7];
    const float* attn_w1 = (const float*)d_in[8];
    const float* diag_w  = (const float*)d_in[9];
    const float* k_attW  = (const float*)d_in[10];
    const float* k_maxW  = (const float*)d_in[11];
    float* out = (float*)d_out;

    static cudaStream_t s2 = 0, s3 = 0;
    static cudaEvent_t  eF = 0, eJ2 = 0, eJ3 = 0;
    if (!s2) {
        cudaFuncSetAttribute(k_mpool_mma, cudaFuncAttributeMaxDynamicSharedMemorySize, 100352);
        cudaFuncSetAttribute(k_algt_mma,  cudaFuncAttributeMaxDynamicSharedMemorySize, 131072);
        cudaStreamCreateWithFlags(&s2, cudaStreamNonBlocking);
        cudaStreamCreateWithFlags(&s3, cudaStreamNonBlocking);
        cudaEventCreateWithFlags(&eF,  cudaEventDisableTiming);
        cudaEventCreateWithFlags(&eJ2, cudaEventDisableTiming);
        cudaEventCreateWithFlags(&eJ3, cudaEventDisableTiming);
    }

    // main: split L first (needed by mpool AND algt_mma), then fork
    k_split<<<dim3(8, B), 256>>>(reps_lt, 0);
    cudaEventRecord(eF, 0);
    cudaStreamWaitEvent(s2, eF, 0);
    cudaStreamWaitEvent(s3, eF, 0);

    // main stream: dominant tensor-core chain (cols 65..128)
    k_mpool_mma<<<dim3(64, B), 256, 100352>>>(reps_rt, k_mpW, out);

    // s2: attentive path -> mp3 mode1 (cols 129..193)
    k_split<<<dim3(8, B), 256, 0, s2>>>(reps_rt, 1);
    k_splitW<<<8, 256, 0, s2>>>(attn_w1);
    k_algt_mma<<<64, 256, 131072, s2>>>(diag_w);
    k_score<<<dim3(8, B), 256, 0, s2>>>();
    k_pr<<<dim3(32, B), 256, 0, s2>>>(reps_rt);
    k_mp3<<<256, 256, 0, s2>>>(reps_lt, h_rt_fw, h_rt_bw, k_attW, reps_rt, out, 1, 129);

    // s3: full match (cols 0..64) + max-attentive -> mp3 mode2 (cols 194..258)
    k_mp3<<<256, 256, 0, s3>>>(reps_lt, h_rt_fw, h_rt_bw, k_full, reps_rt, out, 0, 0);
    k_nrt<<<512, 256, 0, s3>>>(reps_rt);
    k_idx<<<dim3(4, B), 256, 0, s3>>>(reps_lt, reps_rt);
    k_mp3<<<256, 256, 0, s3>>>(reps_lt, h_rt_fw, h_rt_bw, k_maxW, reps_rt, out, 2, 194);

    // join side streams back into the main stream
    cudaEventRecord(eJ2, s2);
    cudaEventRecord(eJ3, s3);
    cudaStreamWaitEvent(0, eJ2, 0);
    cudaStreamWaitEvent(0, eJ3, 0);
}